// round 4
// baseline (speedup 1.0000x reference)
#include <cuda_runtime.h>

#define N_NODES 50000
#define N_EDGES 800000
#define D 128

// ---- scratch (device globals; no allocation allowed) ----
__device__ float g_xs[N_NODES * D];     // 25.6 MB: (h @ W) * dinv[row]
__device__ float g_h [N_NODES * D];     // 25.6 MB: layer-1 output
__device__ float g_dinv[N_NODES];
__device__ int   g_deg [N_NODES];
__device__ int   g_off [N_NODES + 1];
__device__ int   g_cur [N_NODES];
__device__ int   g_csr [N_EDGES];       // source node per incoming edge, grouped by target

// ---------------------------------------------------------------------------
__global__ void k_zero_deg() {
    int i = blockIdx.x * blockDim.x + threadIdx.x;
    if (i < N_NODES) g_deg[i] = 0;
}

__global__ void k_hist(const int* __restrict__ col) {
    int e = blockIdx.x * blockDim.x + threadIdx.x;
    if (e < N_EDGES) atomicAdd(&g_deg[col[e]], 1);
}

// Single-block exclusive scan over 50000 degrees + dinv computation.
__global__ void k_scan() {
    __shared__ int part[1024];
    const int CH = (N_NODES + 1023) / 1024;   // 49
    int t  = threadIdx.x;
    int s0 = t * CH;
    int s1 = min(s0 + CH, N_NODES);

    int sum = 0;
    for (int i = s0; i < s1; i++) sum += g_deg[i];
    part[t] = sum;
    __syncthreads();

    // Hillis-Steele inclusive scan
    for (int d2 = 1; d2 < 1024; d2 <<= 1) {
        int v = 0;
        if (t >= d2) v = part[t - d2];
        __syncthreads();
        if (t >= d2) part[t] += v;
        __syncthreads();
    }

    int run = (t > 0) ? part[t - 1] : 0;  // exclusive base for this chunk
    for (int i = s0; i < s1; i++) {
        g_off[i] = run;
        g_cur[i] = run;
        int dg = g_deg[i];
        g_dinv[i] = rsqrtf((float)(dg + 1));   // +1 self loop -> always > 0
        run += dg;
    }
    if (t == 1023) g_off[N_NODES] = part[1023];
}

__global__ void k_build_csr(const int* __restrict__ row, const int* __restrict__ col) {
    int e = blockIdx.x * blockDim.x + threadIdx.x;
    if (e < N_EDGES) {
        int c = col[e];
        int p = atomicAdd(&g_cur[c], 1);
        g_csr[p] = row[e];
    }
}

// ---------------------------------------------------------------------------
// GEMM: out[i,:] = (A[i,:] @ W) * dinv[i].  Block = 128 rows x 128 cols,
// 256 threads, each thread 8x8 outputs, K tiled by 16.
__global__ void __launch_bounds__(256, 2)
k_gemm_scale(const float* __restrict__ A, const float* __restrict__ W,
             float* __restrict__ out) {
    __shared__ float As[128][17];   // +1 pad: conflict-free column reads
    __shared__ float Ws[16][128];

    const int tid = threadIdx.x;
    const int tx  = tid & 15;       // col group: cols tx*8 .. tx*8+7
    const int ty  = tid >> 4;       // row group: rows ty*8 .. ty*8+7
    const int rowBase = blockIdx.x * 128;

    float acc[8][8];
#pragma unroll
    for (int i = 0; i < 8; i++)
#pragma unroll
        for (int j = 0; j < 8; j++) acc[i][j] = 0.f;

    for (int k0 = 0; k0 < D; k0 += 16) {
        // stage A tile [128 x 16]: each thread loads 8 floats of one row
        {
            int r = tid >> 1;
            int h = (tid & 1) * 8;
            int grow = rowBase + r;
            float4 v0 = make_float4(0, 0, 0, 0), v1 = make_float4(0, 0, 0, 0);
            if (grow < N_NODES) {
                v0 = *(const float4*)&A[(size_t)grow * D + k0 + h];
                v1 = *(const float4*)&A[(size_t)grow * D + k0 + h + 4];
            }
            As[r][h + 0] = v0.x; As[r][h + 1] = v0.y; As[r][h + 2] = v0.z; As[r][h + 3] = v0.w;
            As[r][h + 4] = v1.x; As[r][h + 5] = v1.y; As[r][h + 6] = v1.z; As[r][h + 7] = v1.w;
        }
        // stage W tile [16 x 128]
        {
            int wr = tid >> 4;
            int wc = (tid & 15) * 8;
            float4 v0 = *(const float4*)&W[(size_t)(k0 + wr) * D + wc];
            float4 v1 = *(const float4*)&W[(size_t)(k0 + wr) * D + wc + 4];
            *(float4*)&Ws[wr][wc]     = v0;
            *(float4*)&Ws[wr][wc + 4] = v1;
        }
        __syncthreads();

#pragma unroll
        for (int kk = 0; kk < 16; kk++) {
            float a[8], w[8];
#pragma unroll
            for (int i = 0; i < 8; i++) a[i] = As[ty * 8 + i][kk];
            float4 w0 = *(float4*)&Ws[kk][tx * 8];
            float4 w1 = *(float4*)&Ws[kk][tx * 8 + 4];
            w[0] = w0.x; w[1] = w0.y; w[2] = w0.z; w[3] = w0.w;
            w[4] = w1.x; w[5] = w1.y; w[6] = w1.z; w[7] = w1.w;
#pragma unroll
            for (int i = 0; i < 8; i++)
#pragma unroll
                for (int j = 0; j < 8; j++) acc[i][j] = fmaf(a[i], w[j], acc[i][j]);
        }
        __syncthreads();
    }

#pragma unroll
    for (int i = 0; i < 8; i++) {
        int grow = rowBase + ty * 8 + i;
        if (grow < N_NODES) {
            float di = g_dinv[grow];
            float4 o0, o1;
            o0.x = acc[i][0] * di; o0.y = acc[i][1] * di;
            o0.z = acc[i][2] * di; o0.w = acc[i][3] * di;
            o1.x = acc[i][4] * di; o1.y = acc[i][5] * di;
            o1.z = acc[i][6] * di; o1.w = acc[i][7] * di;
            *(float4*)&out[(size_t)grow * D + tx * 8]     = o0;
            *(float4*)&out[(size_t)grow * D + tx * 8 + 4] = o1;
        }
    }
}

// ---------------------------------------------------------------------------
// Gather: one warp per node. acc starts from the self-loop term xs[c].
// out[c] = prelu( dinv[c] * (xs[c] + sum_{incoming e} xs[src(e)]) + b , a )
__global__ void k_gather(const float* __restrict__ xs, const float* __restrict__ b,
                         const float* __restrict__ a, float* __restrict__ out) {
    int node = (blockIdx.x * blockDim.x + threadIdx.x) >> 5;
    int lane = threadIdx.x & 31;
    if (node >= N_NODES) return;
    const int c4 = lane * 4;

    float4 acc = *(const float4*)&xs[(size_t)node * D + c4];   // self loop

    int s = g_off[node];
    int e = g_off[node + 1];
    int i = s;
    // unroll by 2: two independent load chains in flight
    for (; i + 1 < e; i += 2) {
        int r0 = __ldg(&g_csr[i]);
        int r1 = __ldg(&g_csr[i + 1]);
        float4 v0 = *(const float4*)&xs[(size_t)r0 * D + c4];
        float4 v1 = *(const float4*)&xs[(size_t)r1 * D + c4];
        acc.x += v0.x + v1.x; acc.y += v0.y + v1.y;
        acc.z += v0.z + v1.z; acc.w += v0.w + v1.w;
    }
    if (i < e) {
        int r0 = __ldg(&g_csr[i]);
        float4 v0 = *(const float4*)&xs[(size_t)r0 * D + c4];
        acc.x += v0.x; acc.y += v0.y; acc.z += v0.z; acc.w += v0.w;
    }

    float  di = g_dinv[node];
    float4 bb = *(const float4*)&b[c4];
    float4 aa = *(const float4*)&a[c4];
    float4 o;
    o.x = fmaf(di, acc.x, bb.x); o.x = (o.x >= 0.f) ? o.x : aa.x * o.x;
    o.y = fmaf(di, acc.y, bb.y); o.y = (o.y >= 0.f) ? o.y : aa.y * o.y;
    o.z = fmaf(di, acc.z, bb.z); o.z = (o.z >= 0.f) ? o.z : aa.z * o.z;
    o.w = fmaf(di, acc.w, bb.w); o.w = (o.w >= 0.f) ? o.w : aa.w * o.w;
    *(float4*)&out[(size_t)node * D + c4] = o;
}

// ---------------------------------------------------------------------------
extern "C" void kernel_launch(void* const* d_in, const int* in_sizes, int n_in,
                              void* d_out, int out_size) {
    const float* x  = (const float*)d_in[0];
    const int*   ei = (const int*)  d_in[1];
    const float* W1 = (const float*)d_in[2];
    const float* b1 = (const float*)d_in[3];
    const float* a1 = (const float*)d_in[4];
    const float* W2 = (const float*)d_in[5];
    const float* b2 = (const float*)d_in[6];
    const float* a2 = (const float*)d_in[7];
    float* out = (float*)d_out;

    const int* row = ei;             // edge_index[0] = sources
    const int* col = ei + N_EDGES;   // edge_index[1] = targets

    float *xs_ptr, *h_ptr;
    cudaGetSymbolAddress((void**)&xs_ptr, g_xs);
    cudaGetSymbolAddress((void**)&h_ptr,  g_h);

    // CSR build (once; reused by both layers)
    k_zero_deg <<<(N_NODES + 255) / 256, 256>>>();
    k_hist     <<<(N_EDGES + 255) / 256, 256>>>(col);
    k_scan     <<<1, 1024>>>();
    k_build_csr<<<(N_EDGES + 255) / 256, 256>>>(row, col);

    const int gemm_blocks   = (N_NODES + 127) / 128;
    const int gather_blocks = (N_NODES * 32 + 255) / 256;

    // layer 1
    k_gemm_scale<<<gemm_blocks, 256>>>(x, W1, xs_ptr);
    k_gather   <<<gather_blocks, 256>>>(xs_ptr, b1, a1, h_ptr);
    // layer 2
    k_gemm_scale<<<gemm_blocks, 256>>>(h_ptr, W2, xs_ptr);
    k_gather   <<<gather_blocks, 256>>>(xs_ptr, b2, a2, out);
}

// round 5
// speedup vs baseline: 1.0024x; 1.0024x over previous
#include <cuda_runtime.h>

#define N_NODES 50000
#define N_EDGES 800000
#define D 128

// ---- scratch (device globals; no allocation allowed) ----
__device__ float g_xs[N_NODES * D];     // 25.6 MB: (h @ W) * dinv[row]
__device__ float g_h [N_NODES * D];     // 25.6 MB: layer-1 output
__device__ float g_dinv[N_NODES];
__device__ int   g_deg [N_NODES];
__device__ int   g_off [N_NODES + 1];
__device__ int   g_cur [N_NODES];
__device__ int   g_csr [N_EDGES];       // source node per incoming edge, grouped by target

// ---------------------------------------------------------------------------
__global__ void k_zero_deg() {
    int i = blockIdx.x * blockDim.x + threadIdx.x;
    if (i < N_NODES) g_deg[i] = 0;
}

__global__ void k_hist(const int* __restrict__ col) {
    int e = blockIdx.x * blockDim.x + threadIdx.x;
    if (e < N_EDGES) atomicAdd(&g_deg[col[e]], 1);
}

// Single-block exclusive scan over 50000 degrees + dinv computation.
__global__ void k_scan() {
    __shared__ int part[1024];
    const int CH = (N_NODES + 1023) / 1024;   // 49
    int t  = threadIdx.x;
    int s0 = t * CH;
    int s1 = min(s0 + CH, N_NODES);

    int sum = 0;
    for (int i = s0; i < s1; i++) sum += g_deg[i];
    part[t] = sum;
    __syncthreads();

    // Hillis-Steele inclusive scan
    for (int d2 = 1; d2 < 1024; d2 <<= 1) {
        int v = 0;
        if (t >= d2) v = part[t - d2];
        __syncthreads();
        if (t >= d2) part[t] += v;
        __syncthreads();
    }

    int run = (t > 0) ? part[t - 1] : 0;  // exclusive base for this chunk
    for (int i = s0; i < s1; i++) {
        g_off[i] = run;
        g_cur[i] = run;
        int dg = g_deg[i];
        g_dinv[i] = rsqrtf((float)(dg + 1));   // +1 self loop -> always > 0
        run += dg;
    }
    if (t == 1023) g_off[N_NODES] = part[1023];
}

__global__ void k_build_csr(const int* __restrict__ row, const int* __restrict__ col) {
    int e = blockIdx.x * blockDim.x + threadIdx.x;
    if (e < N_EDGES) {
        int c = col[e];
        int p = atomicAdd(&g_cur[c], 1);
        g_csr[p] = row[e];
    }
}

// ---------------------------------------------------------------------------
// GEMM: out[i,:] = (A[i,:] @ W) * dinv[i].  Block = 128 rows x 128 cols,
// 256 threads, each thread 8x8 outputs, K tiled by 16.
__global__ void __launch_bounds__(256, 2)
k_gemm_scale(const float* __restrict__ A, const float* __restrict__ W,
             float* __restrict__ out) {
    __shared__ float As[128][17];   // +1 pad: conflict-free column reads
    __shared__ float Ws[16][128];

    const int tid = threadIdx.x;
    const int tx  = tid & 15;       // col group: cols tx*8 .. tx*8+7
    const int ty  = tid >> 4;       // row group: rows ty*8 .. ty*8+7
    const int rowBase = blockIdx.x * 128;

    float acc[8][8];
#pragma unroll
    for (int i = 0; i < 8; i++)
#pragma unroll
        for (int j = 0; j < 8; j++) acc[i][j] = 0.f;

    for (int k0 = 0; k0 < D; k0 += 16) {
        // stage A tile [128 x 16]: each thread loads 8 floats of one row
        {
            int r = tid >> 1;
            int h = (tid & 1) * 8;
            int grow = rowBase + r;
            float4 v0 = make_float4(0, 0, 0, 0), v1 = make_float4(0, 0, 0, 0);
            if (grow < N_NODES) {
                v0 = *(const float4*)&A[(size_t)grow * D + k0 + h];
                v1 = *(const float4*)&A[(size_t)grow * D + k0 + h + 4];
            }
            As[r][h + 0] = v0.x; As[r][h + 1] = v0.y; As[r][h + 2] = v0.z; As[r][h + 3] = v0.w;
            As[r][h + 4] = v1.x; As[r][h + 5] = v1.y; As[r][h + 6] = v1.z; As[r][h + 7] = v1.w;
        }
        // stage W tile [16 x 128]
        {
            int wr = tid >> 4;
            int wc = (tid & 15) * 8;
            float4 v0 = *(const float4*)&W[(size_t)(k0 + wr) * D + wc];
            float4 v1 = *(const float4*)&W[(size_t)(k0 + wr) * D + wc + 4];
            *(float4*)&Ws[wr][wc]     = v0;
            *(float4*)&Ws[wr][wc + 4] = v1;
        }
        __syncthreads();

#pragma unroll
        for (int kk = 0; kk < 16; kk++) {
            float a[8], w[8];
#pragma unroll
            for (int i = 0; i < 8; i++) a[i] = As[ty * 8 + i][kk];
            float4 w0 = *(float4*)&Ws[kk][tx * 8];
            float4 w1 = *(float4*)&Ws[kk][tx * 8 + 4];
            w[0] = w0.x; w[1] = w0.y; w[2] = w0.z; w[3] = w0.w;
            w[4] = w1.x; w[5] = w1.y; w[6] = w1.z; w[7] = w1.w;
#pragma unroll
            for (int i = 0; i < 8; i++)
#pragma unroll
                for (int j = 0; j < 8; j++) acc[i][j] = fmaf(a[i], w[j], acc[i][j]);
        }
        __syncthreads();
    }

#pragma unroll
    for (int i = 0; i < 8; i++) {
        int grow = rowBase + ty * 8 + i;
        if (grow < N_NODES) {
            float di = g_dinv[grow];
            float4 o0, o1;
            o0.x = acc[i][0] * di; o0.y = acc[i][1] * di;
            o0.z = acc[i][2] * di; o0.w = acc[i][3] * di;
            o1.x = acc[i][4] * di; o1.y = acc[i][5] * di;
            o1.z = acc[i][6] * di; o1.w = acc[i][7] * di;
            *(float4*)&out[(size_t)grow * D + tx * 8]     = o0;
            *(float4*)&out[(size_t)grow * D + tx * 8 + 4] = o1;
        }
    }
}

// ---------------------------------------------------------------------------
// Gather: one warp per node. acc starts from the self-loop term xs[c].
// out[c] = prelu( dinv[c] * (xs[c] + sum_{incoming e} xs[src(e)]) + b , a )
__global__ void k_gather(const float* __restrict__ xs, const float* __restrict__ b,
                         const float* __restrict__ a, float* __restrict__ out) {
    int node = (blockIdx.x * blockDim.x + threadIdx.x) >> 5;
    int lane = threadIdx.x & 31;
    if (node >= N_NODES) return;
    const int c4 = lane * 4;

    float4 acc = *(const float4*)&xs[(size_t)node * D + c4];   // self loop

    int s = g_off[node];
    int e = g_off[node + 1];
    int i = s;
    // unroll by 2: two independent load chains in flight
    for (; i + 1 < e; i += 2) {
        int r0 = __ldg(&g_csr[i]);
        int r1 = __ldg(&g_csr[i + 1]);
        float4 v0 = *(const float4*)&xs[(size_t)r0 * D + c4];
        float4 v1 = *(const float4*)&xs[(size_t)r1 * D + c4];
        acc.x += v0.x + v1.x; acc.y += v0.y + v1.y;
        acc.z += v0.z + v1.z; acc.w += v0.w + v1.w;
    }
    if (i < e) {
        int r0 = __ldg(&g_csr[i]);
        float4 v0 = *(const float4*)&xs[(size_t)r0 * D + c4];
        acc.x += v0.x; acc.y += v0.y; acc.z += v0.z; acc.w += v0.w;
    }

    float  di = g_dinv[node];
    float4 bb = *(const float4*)&b[c4];
    float4 aa = *(const float4*)&a[c4];
    float4 o;
    o.x = fmaf(di, acc.x, bb.x); o.x = (o.x >= 0.f) ? o.x : aa.x * o.x;
    o.y = fmaf(di, acc.y, bb.y); o.y = (o.y >= 0.f) ? o.y : aa.y * o.y;
    o.z = fmaf(di, acc.z, bb.z); o.z = (o.z >= 0.f) ? o.z : aa.z * o.z;
    o.w = fmaf(di, acc.w, bb.w); o.w = (o.w >= 0.f) ? o.w : aa.w * o.w;
    *(float4*)&out[(size_t)node * D + c4] = o;
}

// ---------------------------------------------------------------------------
extern "C" void kernel_launch(void* const* d_in, const int* in_sizes, int n_in,
                              void* d_out, int out_size) {
    const float* x  = (const float*)d_in[0];
    const int*   ei = (const int*)  d_in[1];
    const float* W1 = (const float*)d_in[2];
    const float* b1 = (const float*)d_in[3];
    const float* a1 = (const float*)d_in[4];
    const float* W2 = (const float*)d_in[5];
    const float* b2 = (const float*)d_in[6];
    const float* a2 = (const float*)d_in[7];
    float* out = (float*)d_out;

    const int* row = ei;             // edge_index[0] = sources
    const int* col = ei + N_EDGES;   // edge_index[1] = targets

    float *xs_ptr, *h_ptr;
    cudaGetSymbolAddress((void**)&xs_ptr, g_xs);
    cudaGetSymbolAddress((void**)&h_ptr,  g_h);

    // CSR build (once; reused by both layers)
    k_zero_deg <<<(N_NODES + 255) / 256, 256>>>();
    k_hist     <<<(N_EDGES + 255) / 256, 256>>>(col);
    k_scan     <<<1, 1024>>>();
    k_build_csr<<<(N_EDGES + 255) / 256, 256>>>(row, col);

    const int gemm_blocks   = (N_NODES + 127) / 128;
    const int gather_blocks = (N_NODES * 32 + 255) / 256;

    // layer 1
    k_gemm_scale<<<gemm_blocks, 256>>>(x, W1, xs_ptr);
    k_gather   <<<gather_blocks, 256>>>(xs_ptr, b1, a1, h_ptr);
    // layer 2
    k_gemm_scale<<<gemm_blocks, 256>>>(h_ptr, W2, xs_ptr);
    k_gather   <<<gather_blocks, 256>>>(xs_ptr, b2, a2, out);
}

// round 6
// speedup vs baseline: 1.0788x; 1.0762x over previous
#include <cuda_runtime.h>
#include <cuda_fp16.h>

#define N_NODES 50000
#define N_EDGES 800000
#define D 128

// ---- scratch (device globals; no allocation allowed) ----
__device__ __half g_xsh[N_NODES * D];   // 12.8 MB: (h @ W) * dinv[row], fp16
__device__ float  g_h  [N_NODES * D];   // 25.6 MB: layer-1 output (fp32)
__device__ float  g_dinv[N_NODES];
__device__ int    g_deg [N_NODES];
__device__ int    g_off [N_NODES + 1];
__device__ int    g_cur [N_NODES];
__device__ int    g_csr [N_EDGES];      // source node per incoming edge, grouped by target

// ---------------------------------------------------------------------------
// Histogram of in-degrees, 4 edges per thread (N_EDGES % 4 == 0).
__global__ void k_hist(const int4* __restrict__ col4) {
    int i = blockIdx.x * blockDim.x + threadIdx.x;
    if (i < N_EDGES / 4) {
        int4 c = __ldg(&col4[i]);
        atomicAdd(&g_deg[c.x], 1);
        atomicAdd(&g_deg[c.y], 1);
        atomicAdd(&g_deg[c.z], 1);
        atomicAdd(&g_deg[c.w], 1);
    }
}

// Single-block exclusive scan over 50000 degrees + dinv computation.
__global__ void k_scan() {
    __shared__ int part[1024];
    const int CH = (N_NODES + 1023) / 1024;   // 49
    int t  = threadIdx.x;
    int s0 = t * CH;
    int s1 = min(s0 + CH, N_NODES);

    int sum = 0;
    for (int i = s0; i < s1; i++) sum += g_deg[i];
    part[t] = sum;
    __syncthreads();

    for (int d2 = 1; d2 < 1024; d2 <<= 1) {
        int v = 0;
        if (t >= d2) v = part[t - d2];
        __syncthreads();
        if (t >= d2) part[t] += v;
        __syncthreads();
    }

    int run = (t > 0) ? part[t - 1] : 0;
    for (int i = s0; i < s1; i++) {
        g_off[i] = run;
        g_cur[i] = run;
        int dg = g_deg[i];
        g_dinv[i] = rsqrtf((float)(dg + 1));   // +1 self loop -> always > 0
        run += dg;
    }
    if (t == 1023) g_off[N_NODES] = part[1023];
}

__global__ void k_build_csr(const int4* __restrict__ row4, const int4* __restrict__ col4) {
    int i = blockIdx.x * blockDim.x + threadIdx.x;
    if (i < N_EDGES / 4) {
        int4 r = __ldg(&row4[i]);
        int4 c = __ldg(&col4[i]);
        g_csr[atomicAdd(&g_cur[c.x], 1)] = r.x;
        g_csr[atomicAdd(&g_cur[c.y], 1)] = r.y;
        g_csr[atomicAdd(&g_cur[c.z], 1)] = r.z;
        g_csr[atomicAdd(&g_cur[c.w], 1)] = r.w;
    }
}

// ---------------------------------------------------------------------------
// GEMM: out_h[i,:] = fp16( (A[i,:] @ W) * dinv[i] ).  Block = 128x128,
// 256 threads, each thread 8x8 outputs, K tiled by 16.
__global__ void __launch_bounds__(256, 2)
k_gemm_scale(const float* __restrict__ A, const float* __restrict__ W,
             __half* __restrict__ out) {
    __shared__ float As[128][17];   // +1 pad: conflict-free column reads
    __shared__ float Ws[16][128];

    const int tid = threadIdx.x;
    const int tx  = tid & 15;
    const int ty  = tid >> 4;
    const int rowBase = blockIdx.x * 128;

    float acc[8][8];
#pragma unroll
    for (int i = 0; i < 8; i++)
#pragma unroll
        for (int j = 0; j < 8; j++) acc[i][j] = 0.f;

    for (int k0 = 0; k0 < D; k0 += 16) {
        {
            int r = tid >> 1;
            int h = (tid & 1) * 8;
            int grow = rowBase + r;
            float4 v0 = make_float4(0, 0, 0, 0), v1 = make_float4(0, 0, 0, 0);
            if (grow < N_NODES) {
                v0 = *(const float4*)&A[(size_t)grow * D + k0 + h];
                v1 = *(const float4*)&A[(size_t)grow * D + k0 + h + 4];
            }
            As[r][h + 0] = v0.x; As[r][h + 1] = v0.y; As[r][h + 2] = v0.z; As[r][h + 3] = v0.w;
            As[r][h + 4] = v1.x; As[r][h + 5] = v1.y; As[r][h + 6] = v1.z; As[r][h + 7] = v1.w;
        }
        {
            int wr = tid >> 4;
            int wc = (tid & 15) * 8;
            float4 v0 = *(const float4*)&W[(size_t)(k0 + wr) * D + wc];
            float4 v1 = *(const float4*)&W[(size_t)(k0 + wr) * D + wc + 4];
            *(float4*)&Ws[wr][wc]     = v0;
            *(float4*)&Ws[wr][wc + 4] = v1;
        }
        __syncthreads();

#pragma unroll
        for (int kk = 0; kk < 16; kk++) {
            float a[8], w[8];
#pragma unroll
            for (int i = 0; i < 8; i++) a[i] = As[ty * 8 + i][kk];
            float4 w0 = *(float4*)&Ws[kk][tx * 8];
            float4 w1 = *(float4*)&Ws[kk][tx * 8 + 4];
            w[0] = w0.x; w[1] = w0.y; w[2] = w0.z; w[3] = w0.w;
            w[4] = w1.x; w[5] = w1.y; w[6] = w1.z; w[7] = w1.w;
#pragma unroll
            for (int i = 0; i < 8; i++)
#pragma unroll
                for (int j = 0; j < 8; j++) acc[i][j] = fmaf(a[i], w[j], acc[i][j]);
        }
        __syncthreads();
    }

#pragma unroll
    for (int i = 0; i < 8; i++) {
        int grow = rowBase + ty * 8 + i;
        if (grow < N_NODES) {
            float di = g_dinv[grow];
            union { __half2 h2[4]; uint4 u; } pk;
            pk.h2[0] = __floats2half2_rn(acc[i][0] * di, acc[i][1] * di);
            pk.h2[1] = __floats2half2_rn(acc[i][2] * di, acc[i][3] * di);
            pk.h2[2] = __floats2half2_rn(acc[i][4] * di, acc[i][5] * di);
            pk.h2[3] = __floats2half2_rn(acc[i][6] * di, acc[i][7] * di);
            *(uint4*)&out[(size_t)grow * D + tx * 8] = pk.u;
        }
    }
}

// ---------------------------------------------------------------------------
// Load 4 consecutive fp16 features of row r at half-offset c4, as float4.
__device__ __forceinline__ float4 ld_row4(const __half* __restrict__ xs, int r, int c4) {
    uint2 u = __ldg((const uint2*)(xs + (size_t)r * D + c4));
    __half2 h0 = *(__half2*)&u.x;
    __half2 h1 = *(__half2*)&u.y;
    float2 a0 = __half22float2(h0);
    float2 a1 = __half22float2(h1);
    return make_float4(a0.x, a0.y, a1.x, a1.y);
}

// Gather: one warp per node, fp32 accumulation over fp16 messages.
// out[c] = prelu( dinv[c] * (xs[c] + sum_{incoming e} xs[src(e)]) + b , a )
__global__ void k_gather(const __half* __restrict__ xs, const float* __restrict__ b,
                         const float* __restrict__ a, float* __restrict__ out) {
    int node = (blockIdx.x * blockDim.x + threadIdx.x) >> 5;
    int lane = threadIdx.x & 31;
    if (node >= N_NODES) return;
    const int c4 = lane * 4;

    float4 acc = ld_row4(xs, node, c4);   // self loop

    int s = g_off[node];
    int e = g_off[node + 1];
    int i = s;
    // unroll by 4: four independent load chains in flight
    for (; i + 4 <= e; i += 4) {
        int r0 = __ldg(&g_csr[i]);
        int r1 = __ldg(&g_csr[i + 1]);
        int r2 = __ldg(&g_csr[i + 2]);
        int r3 = __ldg(&g_csr[i + 3]);
        float4 v0 = ld_row4(xs, r0, c4);
        float4 v1 = ld_row4(xs, r1, c4);
        float4 v2 = ld_row4(xs, r2, c4);
        float4 v3 = ld_row4(xs, r3, c4);
        acc.x += (v0.x + v1.x) + (v2.x + v3.x);
        acc.y += (v0.y + v1.y) + (v2.y + v3.y);
        acc.z += (v0.z + v1.z) + (v2.z + v3.z);
        acc.w += (v0.w + v1.w) + (v2.w + v3.w);
    }
    for (; i < e; i++) {
        int r0 = __ldg(&g_csr[i]);
        float4 v0 = ld_row4(xs, r0, c4);
        acc.x += v0.x; acc.y += v0.y; acc.z += v0.z; acc.w += v0.w;
    }

    float  di = g_dinv[node];
    float4 bb = *(const float4*)&b[c4];
    float4 aa = *(const float4*)&a[c4];
    float4 o;
    o.x = fmaf(di, acc.x, bb.x); o.x = (o.x >= 0.f) ? o.x : aa.x * o.x;
    o.y = fmaf(di, acc.y, bb.y); o.y = (o.y >= 0.f) ? o.y : aa.y * o.y;
    o.z = fmaf(di, acc.z, bb.z); o.z = (o.z >= 0.f) ? o.z : aa.z * o.z;
    o.w = fmaf(di, acc.w, bb.w); o.w = (o.w >= 0.f) ? o.w : aa.w * o.w;
    *(float4*)&out[(size_t)node * D + c4] = o;
}

// ---------------------------------------------------------------------------
extern "C" void kernel_launch(void* const* d_in, const int* in_sizes, int n_in,
                              void* d_out, int out_size) {
    const float* x  = (const float*)d_in[0];
    const int*   ei = (const int*)  d_in[1];
    const float* W1 = (const float*)d_in[2];
    const float* b1 = (const float*)d_in[3];
    const float* a1 = (const float*)d_in[4];
    const float* W2 = (const float*)d_in[5];
    const float* b2 = (const float*)d_in[6];
    const float* a2 = (const float*)d_in[7];
    float* out = (float*)d_out;

    const int4* row4 = (const int4*)ei;               // edge_index[0] = sources
    const int4* col4 = (const int4*)(ei + N_EDGES);   // edge_index[1] = targets

    __half *xs_ptr;  float *h_ptr;  int *deg_ptr;
    cudaGetSymbolAddress((void**)&xs_ptr,  g_xsh);
    cudaGetSymbolAddress((void**)&h_ptr,   g_h);
    cudaGetSymbolAddress((void**)&deg_ptr, g_deg);

    // CSR build (once; reused by both layers)
    cudaMemsetAsync(deg_ptr, 0, N_NODES * sizeof(int), 0);
    const int e4blocks = (N_EDGES / 4 + 255) / 256;
    k_hist     <<<e4blocks, 256>>>(col4);
    k_scan     <<<1, 1024>>>();
    k_build_csr<<<e4blocks, 256>>>(row4, col4);

    const int gemm_blocks   = (N_NODES + 127) / 128;
    const int gather_blocks = (N_NODES * 32 + 255) / 256;

    // layer 1
    k_gemm_scale<<<gemm_blocks, 256>>>(x, W1, xs_ptr);
    k_gather   <<<gather_blocks, 256>>>(xs_ptr, b1, a1, h_ptr);
    // layer 2
    k_gemm_scale<<<gemm_blocks, 256>>>(h_ptr, W2, xs_ptr);
    k_gather   <<<gather_blocks, 256>>>(xs_ptr, b2, a2, out);
}

// round 7
// speedup vs baseline: 1.0803x; 1.0014x over previous
#include <cuda_runtime.h>
#include <cuda_fp16.h>

#define N_NODES 50000
#define N_EDGES 800000
#define D 128

// ---- scratch (device globals; no allocation allowed) ----
__device__ __half g_xsh[N_NODES * D];   // 12.8 MB: (h @ W) * dinv[row], fp16
__device__ float  g_h  [N_NODES * D];   // 25.6 MB: layer-1 output (fp32)
__device__ float  g_dinv[N_NODES];
__device__ int    g_deg [N_NODES];
__device__ int    g_off [N_NODES + 1];
__device__ int    g_cur [N_NODES];
__device__ int    g_csr [N_EDGES];      // source node per incoming edge, grouped by target

// ---------------------------------------------------------------------------
// Histogram of in-degrees, 4 edges per thread (N_EDGES % 4 == 0).
__global__ void k_hist(const int4* __restrict__ col4) {
    int i = blockIdx.x * blockDim.x + threadIdx.x;
    if (i < N_EDGES / 4) {
        int4 c = __ldg(&col4[i]);
        atomicAdd(&g_deg[c.x], 1);
        atomicAdd(&g_deg[c.y], 1);
        atomicAdd(&g_deg[c.z], 1);
        atomicAdd(&g_deg[c.w], 1);
    }
}

// Single-block exclusive scan over 50000 degrees + dinv computation.
__global__ void k_scan() {
    __shared__ int part[1024];
    const int CH = (N_NODES + 1023) / 1024;   // 49
    int t  = threadIdx.x;
    int s0 = t * CH;
    int s1 = min(s0 + CH, N_NODES);

    int sum = 0;
    for (int i = s0; i < s1; i++) sum += g_deg[i];
    part[t] = sum;
    __syncthreads();

    for (int d2 = 1; d2 < 1024; d2 <<= 1) {
        int v = 0;
        if (t >= d2) v = part[t - d2];
        __syncthreads();
        if (t >= d2) part[t] += v;
        __syncthreads();
    }

    int run = (t > 0) ? part[t - 1] : 0;
    for (int i = s0; i < s1; i++) {
        g_off[i] = run;
        g_cur[i] = run;
        int dg = g_deg[i];
        g_dinv[i] = rsqrtf((float)(dg + 1));   // +1 self loop -> always > 0
        run += dg;
    }
    if (t == 1023) g_off[N_NODES] = part[1023];
}

__global__ void k_build_csr(const int4* __restrict__ row4, const int4* __restrict__ col4) {
    int i = blockIdx.x * blockDim.x + threadIdx.x;
    if (i < N_EDGES / 4) {
        int4 r = __ldg(&row4[i]);
        int4 c = __ldg(&col4[i]);
        g_csr[atomicAdd(&g_cur[c.x], 1)] = r.x;
        g_csr[atomicAdd(&g_cur[c.y], 1)] = r.y;
        g_csr[atomicAdd(&g_cur[c.z], 1)] = r.z;
        g_csr[atomicAdd(&g_cur[c.w], 1)] = r.w;
    }
}

// ---------------------------------------------------------------------------
// GEMM: out_h[i,:] = fp16( (A[i,:] @ W) * dinv[i] ).  Block = 128x128,
// 256 threads, each thread 8x8 outputs, K tiled by 16.
__global__ void __launch_bounds__(256, 2)
k_gemm_scale(const float* __restrict__ A, const float* __restrict__ W,
             __half* __restrict__ out) {
    __shared__ float As[128][17];   // +1 pad: conflict-free column reads
    __shared__ float Ws[16][128];

    const int tid = threadIdx.x;
    const int tx  = tid & 15;
    const int ty  = tid >> 4;
    const int rowBase = blockIdx.x * 128;

    float acc[8][8];
#pragma unroll
    for (int i = 0; i < 8; i++)
#pragma unroll
        for (int j = 0; j < 8; j++) acc[i][j] = 0.f;

    for (int k0 = 0; k0 < D; k0 += 16) {
        {
            int r = tid >> 1;
            int h = (tid & 1) * 8;
            int grow = rowBase + r;
            float4 v0 = make_float4(0, 0, 0, 0), v1 = make_float4(0, 0, 0, 0);
            if (grow < N_NODES) {
                v0 = *(const float4*)&A[(size_t)grow * D + k0 + h];
                v1 = *(const float4*)&A[(size_t)grow * D + k0 + h + 4];
            }
            As[r][h + 0] = v0.x; As[r][h + 1] = v0.y; As[r][h + 2] = v0.z; As[r][h + 3] = v0.w;
            As[r][h + 4] = v1.x; As[r][h + 5] = v1.y; As[r][h + 6] = v1.z; As[r][h + 7] = v1.w;
        }
        {
            int wr = tid >> 4;
            int wc = (tid & 15) * 8;
            float4 v0 = *(const float4*)&W[(size_t)(k0 + wr) * D + wc];
            float4 v1 = *(const float4*)&W[(size_t)(k0 + wr) * D + wc + 4];
            *(float4*)&Ws[wr][wc]     = v0;
            *(float4*)&Ws[wr][wc + 4] = v1;
        }
        __syncthreads();

#pragma unroll
        for (int kk = 0; kk < 16; kk++) {
            float a[8], w[8];
#pragma unroll
            for (int i = 0; i < 8; i++) a[i] = As[ty * 8 + i][kk];
            float4 w0 = *(float4*)&Ws[kk][tx * 8];
            float4 w1 = *(float4*)&Ws[kk][tx * 8 + 4];
            w[0] = w0.x; w[1] = w0.y; w[2] = w0.z; w[3] = w0.w;
            w[4] = w1.x; w[5] = w1.y; w[6] = w1.z; w[7] = w1.w;
#pragma unroll
            for (int i = 0; i < 8; i++)
#pragma unroll
                for (int j = 0; j < 8; j++) acc[i][j] = fmaf(a[i], w[j], acc[i][j]);
        }
        __syncthreads();
    }

#pragma unroll
    for (int i = 0; i < 8; i++) {
        int grow = rowBase + ty * 8 + i;
        if (grow < N_NODES) {
            float di = g_dinv[grow];
            union { __half2 h2[4]; uint4 u; } pk;
            pk.h2[0] = __floats2half2_rn(acc[i][0] * di, acc[i][1] * di);
            pk.h2[1] = __floats2half2_rn(acc[i][2] * di, acc[i][3] * di);
            pk.h2[2] = __floats2half2_rn(acc[i][4] * di, acc[i][5] * di);
            pk.h2[3] = __floats2half2_rn(acc[i][6] * di, acc[i][7] * di);
            *(uint4*)&out[(size_t)grow * D + tx * 8] = pk.u;
        }
    }
}

// ---------------------------------------------------------------------------
// Load 4 consecutive fp16 features of row r at half-offset c4, as float4.
__device__ __forceinline__ float4 ld_row4(const __half* __restrict__ xs, int r, int c4) {
    uint2 u = __ldg((const uint2*)(xs + (size_t)r * D + c4));
    __half2 h0 = *(__half2*)&u.x;
    __half2 h1 = *(__half2*)&u.y;
    float2 a0 = __half22float2(h0);
    float2 a1 = __half22float2(h1);
    return make_float4(a0.x, a0.y, a1.x, a1.y);
}

// Gather: one warp per node, fp32 accumulation over fp16 messages.
// out[c] = prelu( dinv[c] * (xs[c] + sum_{incoming e} xs[src(e)]) + b , a )
__global__ void k_gather(const __half* __restrict__ xs, const float* __restrict__ b,
                         const float* __restrict__ a, float* __restrict__ out) {
    int node = (blockIdx.x * blockDim.x + threadIdx.x) >> 5;
    int lane = threadIdx.x & 31;
    if (node >= N_NODES) return;
    const int c4 = lane * 4;

    float4 acc = ld_row4(xs, node, c4);   // self loop

    int s = g_off[node];
    int e = g_off[node + 1];
    int i = s;
    // unroll by 4: four independent load chains in flight
    for (; i + 4 <= e; i += 4) {
        int r0 = __ldg(&g_csr[i]);
        int r1 = __ldg(&g_csr[i + 1]);
        int r2 = __ldg(&g_csr[i + 2]);
        int r3 = __ldg(&g_csr[i + 3]);
        float4 v0 = ld_row4(xs, r0, c4);
        float4 v1 = ld_row4(xs, r1, c4);
        float4 v2 = ld_row4(xs, r2, c4);
        float4 v3 = ld_row4(xs, r3, c4);
        acc.x += (v0.x + v1.x) + (v2.x + v3.x);
        acc.y += (v0.y + v1.y) + (v2.y + v3.y);
        acc.z += (v0.z + v1.z) + (v2.z + v3.z);
        acc.w += (v0.w + v1.w) + (v2.w + v3.w);
    }
    for (; i < e; i++) {
        int r0 = __ldg(&g_csr[i]);
        float4 v0 = ld_row4(xs, r0, c4);
        acc.x += v0.x; acc.y += v0.y; acc.z += v0.z; acc.w += v0.w;
    }

    float  di = g_dinv[node];
    float4 bb = *(const float4*)&b[c4];
    float4 aa = *(const float4*)&a[c4];
    float4 o;
    o.x = fmaf(di, acc.x, bb.x); o.x = (o.x >= 0.f) ? o.x : aa.x * o.x;
    o.y = fmaf(di, acc.y, bb.y); o.y = (o.y >= 0.f) ? o.y : aa.y * o.y;
    o.z = fmaf(di, acc.z, bb.z); o.z = (o.z >= 0.f) ? o.z : aa.z * o.z;
    o.w = fmaf(di, acc.w, bb.w); o.w = (o.w >= 0.f) ? o.w : aa.w * o.w;
    *(float4*)&out[(size_t)node * D + c4] = o;
}

// ---------------------------------------------------------------------------
extern "C" void kernel_launch(void* const* d_in, const int* in_sizes, int n_in,
                              void* d_out, int out_size) {
    const float* x  = (const float*)d_in[0];
    const int*   ei = (const int*)  d_in[1];
    const float* W1 = (const float*)d_in[2];
    const float* b1 = (const float*)d_in[3];
    const float* a1 = (const float*)d_in[4];
    const float* W2 = (const float*)d_in[5];
    const float* b2 = (const float*)d_in[6];
    const float* a2 = (const float*)d_in[7];
    float* out = (float*)d_out;

    const int4* row4 = (const int4*)ei;               // edge_index[0] = sources
    const int4* col4 = (const int4*)(ei + N_EDGES);   // edge_index[1] = targets

    __half *xs_ptr;  float *h_ptr;  int *deg_ptr;
    cudaGetSymbolAddress((void**)&xs_ptr,  g_xsh);
    cudaGetSymbolAddress((void**)&h_ptr,   g_h);
    cudaGetSymbolAddress((void**)&deg_ptr, g_deg);

    // CSR build (once; reused by both layers)
    cudaMemsetAsync(deg_ptr, 0, N_NODES * sizeof(int), 0);
    const int e4blocks = (N_EDGES / 4 + 255) / 256;
    k_hist     <<<e4blocks, 256>>>(col4);
    k_scan     <<<1, 1024>>>();
    k_build_csr<<<e4blocks, 256>>>(row4, col4);

    const int gemm_blocks   = (N_NODES + 127) / 128;
    const int gather_blocks = (N_NODES * 32 + 255) / 256;

    // layer 1
    k_gemm_scale<<<gemm_blocks, 256>>>(x, W1, xs_ptr);
    k_gather   <<<gather_blocks, 256>>>(xs_ptr, b1, a1, h_ptr);
    // layer 2
    k_gemm_scale<<<gemm_blocks, 256>>>(h_ptr, W2, xs_ptr);
    k_gather   <<<gather_blocks, 256>>>(xs_ptr, b2, a2, out);
}